// round 2
// baseline (speedup 1.0000x reference)
#include <cuda_runtime.h>
#include <math.h>

#define DM 512
#define DI 2048
#define NH 8
#define DKH 64
#define BSZ 32
#define MAXROWS (32*160)
#define MAXKV   (32*640)

// ---- scratch (device globals; no allocation allowed) ----
__device__ float g_Q  [MAXROWS*DM];
__device__ float g_K  [MAXKV*DM];
__device__ float g_V  [MAXKV*DM];
__device__ float g_ctx[MAXROWS*DM];
__device__ float g_t0 [MAXROWS*DM];   // fc out, later ffn2 out
__device__ float g_x  [MAXROWS*DM];   // post-ln1
__device__ float g_h  [MAXROWS*DI];   // ffn hidden

// ============================================================
// SGEMM: C[M,N] = A[M,K] * W[N,K]^T + bias[N], optional relu,
// optional row gather on A (rmap). BM=BN=64, BK=16, 256 thr, 4x4/thr.
// ============================================================
__global__ void sgemm_nt(const float* __restrict__ A, const int* __restrict__ rmap,
                         const float* __restrict__ W, const float* __restrict__ bias,
                         float* __restrict__ C, int M, int N, int K, int relu)
{
    __shared__ float As[16][68];
    __shared__ float Ws[16][68];
    const int tid = threadIdx.x;
    const int bm = blockIdx.y * 64, bn = blockIdx.x * 64;
    const int lr = tid >> 2;            // 0..63 tile row for loading
    const int lk = (tid & 3) << 2;      // 0,4,8,12
    const int ty = tid >> 4, tx = tid & 15;

    float acc[4][4];
    #pragma unroll
    for (int i = 0; i < 4; ++i)
        #pragma unroll
        for (int j = 0; j < 4; ++j) acc[i][j] = 0.f;

    int arow = bm + lr;
    const float4* Ap = nullptr;
    if (arow < M) {
        int g = rmap ? rmap[arow] : arow;
        Ap = (const float4*)(A + (size_t)g * K);
    }
    int wrow = bn + lr;
    const float4* Wp = (wrow < N) ? (const float4*)(W + (size_t)wrow * K) : nullptr;

    for (int k0 = 0; k0 < K; k0 += 16) {
        float4 av = Ap ? Ap[(k0 + lk) >> 2] : make_float4(0.f,0.f,0.f,0.f);
        float4 wv = Wp ? Wp[(k0 + lk) >> 2] : make_float4(0.f,0.f,0.f,0.f);
        As[lk+0][lr]=av.x; As[lk+1][lr]=av.y; As[lk+2][lr]=av.z; As[lk+3][lr]=av.w;
        Ws[lk+0][lr]=wv.x; Ws[lk+1][lr]=wv.y; Ws[lk+2][lr]=wv.z; Ws[lk+3][lr]=wv.w;
        __syncthreads();
        #pragma unroll
        for (int kk = 0; kk < 16; ++kk) {
            float4 a4 = *(const float4*)&As[kk][ty*4];
            float4 w4 = *(const float4*)&Ws[kk][tx*4];
            acc[0][0] += a4.x*w4.x; acc[0][1] += a4.x*w4.y; acc[0][2] += a4.x*w4.z; acc[0][3] += a4.x*w4.w;
            acc[1][0] += a4.y*w4.x; acc[1][1] += a4.y*w4.y; acc[1][2] += a4.y*w4.z; acc[1][3] += a4.y*w4.w;
            acc[2][0] += a4.z*w4.x; acc[2][1] += a4.z*w4.y; acc[2][2] += a4.z*w4.z; acc[2][3] += a4.z*w4.w;
            acc[3][0] += a4.w*w4.x; acc[3][1] += a4.w*w4.y; acc[3][2] += a4.w*w4.z; acc[3][3] += a4.w*w4.w;
        }
        __syncthreads();
    }

    #pragma unroll
    for (int i = 0; i < 4; ++i) {
        int cm = bm + ty*4 + i;
        if (cm >= M) continue;
        #pragma unroll
        for (int j = 0; j < 4; ++j) {
            int cn = bn + tx*4 + j;
            if (cn >= N) continue;
            float v = acc[i][j] + bias[cn];
            if (relu) v = fmaxf(v, 0.f);
            C[(size_t)cm*N + cn] = v;
        }
    }
}

// ============================================================
// LayerNorm with residual: out[row] = LN(A[row] + R[rmap?rmap[row]:row])
// 128 threads/row, 512 elems.
// ============================================================
__global__ void ln_res(const float* __restrict__ A, const float* __restrict__ R,
                       const int* __restrict__ rmap,
                       const float* __restrict__ g, const float* __restrict__ beta,
                       float* __restrict__ out)
{
    int row = blockIdx.x;
    int tid = threadIdx.x;   // 128
    __shared__ float red [128];
    __shared__ float red2[128];
    int rrow = rmap ? rmap[row] : row;
    float4 x = ((const float4*)(A + (size_t)row*DM))[tid];
    float4 r = ((const float4*)(R + (size_t)rrow*DM))[tid];
    x.x += r.x; x.y += r.y; x.z += r.z; x.w += r.w;
    red [tid] = x.x + x.y + x.z + x.w;
    red2[tid] = x.x*x.x + x.y*x.y + x.z*x.z + x.w*x.w;
    __syncthreads();
    #pragma unroll
    for (int o = 64; o > 0; o >>= 1) {
        if (tid < o) { red[tid] += red[tid+o]; red2[tid] += red2[tid+o]; }
        __syncthreads();
    }
    float mean = red[0] * (1.f/512.f);
    float var  = red2[0] * (1.f/512.f) - mean*mean;
    float inv  = rsqrtf(var + 1e-5f);
    float4 gg = ((const float4*)g)[tid];
    float4 bb = ((const float4*)beta)[tid];
    float4 o4;
    o4.x = (x.x - mean)*inv*gg.x + bb.x;
    o4.y = (x.y - mean)*inv*gg.y + bb.y;
    o4.z = (x.z - mean)*inv*gg.z + bb.z;
    o4.w = (x.w - mean)*inv*gg.w + bb.w;
    ((float4*)(out + (size_t)row*DM))[tid] = o4;
}

// ============================================================
// Attention: one block per (gathered row m, head h). 128 threads.
// Two-pass softmax over Lv (<=640) keys with mask (nonzero = masked/-inf).
// Mask is read as 4-byte elements (int32 or float32 both test correctly).
// ============================================================
__global__ void attn_kernel(const float* __restrict__ Q, const float* __restrict__ Kb,
                            const float* __restrict__ Vb,
                            const int* __restrict__ mask,
                            const int* __restrict__ gidx,
                            float* __restrict__ ctx, int Lq, int Lv)
{
    int m = blockIdx.x, h = blockIdx.y;
    int tid = threadIdx.x;   // 128
    __shared__ float qv[64];
    __shared__ float sc[640];
    __shared__ float red[128];

    int row = gidx[m];
    int b = row / Lq, qi = row - b * Lq;

    if (tid < 16)
        ((float4*)qv)[tid] = ((const float4*)(Q + (size_t)m*DM + h*DKH))[tid];
    __syncthreads();

    const int* mrow = mask + ((size_t)b*Lq + qi) * Lv;
    const float* Krow = Kb + ((size_t)b*Lv)*DM + h*DKH;

    float lmax = -INFINITY;
    for (int j = tid; j < Lv; j += 128) {
        float s;
        if (mrow[j] != 0) s = -INFINITY;
        else {
            const float4* kp = (const float4*)(Krow + (size_t)j*DM);
            float acc = 0.f;
            #pragma unroll
            for (int d = 0; d < 16; ++d) {
                float4 kv = kp[d];
                float4 q4 = ((const float4*)qv)[d];
                acc += kv.x*q4.x + kv.y*q4.y + kv.z*q4.z + kv.w*q4.w;
            }
            s = acc * 0.125f;
        }
        sc[j] = s;
        lmax = fmaxf(lmax, s);
    }
    red[tid] = lmax; __syncthreads();
    #pragma unroll
    for (int o = 64; o > 0; o >>= 1) {
        if (tid < o) red[tid] = fmaxf(red[tid], red[tid+o]);
        __syncthreads();
    }
    float mx = red[0];
    __syncthreads();

    float lsum = 0.f;
    for (int j = tid; j < Lv; j += 128) {
        float e = __expf(sc[j] - mx);
        sc[j] = e;
        lsum += e;
    }
    red[tid] = lsum; __syncthreads();
    #pragma unroll
    for (int o = 64; o > 0; o >>= 1) {
        if (tid < o) red[tid] += red[tid+o];
        __syncthreads();
    }
    float inv = 1.f / red[0];
    __syncthreads();

    // weighted V sum: 64 output dims, split Lv between two half-groups
    int d = tid & 63, half = tid >> 6;
    const float* Vrow = Vb + ((size_t)b*Lv)*DM + h*DKH + d;
    float acc = 0.f;
    for (int j = half; j < Lv; j += 2)
        acc += sc[j] * Vrow[(size_t)j*DM];
    red[tid] = acc; __syncthreads();
    if (half == 0)
        ctx[(size_t)m*DM + h*DKH + d] = (red[tid] + red[tid+64]) * inv;
}

// ============================================================
// launcher
// ============================================================
extern "C" void kernel_launch(void* const* d_in, const int* in_sizes, int n_in,
                              void* d_out, int out_size)
{
    const float* ent   = (const float*)d_in[0];
    const float* pred  = (const float*)d_in[1];
    const float* w_qs  = (const float*)d_in[2];
    const float* b_qs  = (const float*)d_in[3];
    const float* w_ks  = (const float*)d_in[4];
    const float* b_ks  = (const float*)d_in[5];
    const float* w_vs  = (const float*)d_in[6];
    const float* b_vs  = (const float*)d_in[7];
    const float* w_fc  = (const float*)d_in[8];
    const float* b_fc  = (const float*)d_in[9];
    const float* ln1_g = (const float*)d_in[10];
    const float* ln1_b = (const float*)d_in[11];
    const float* w1    = (const float*)d_in[12];
    const float* b1    = (const float*)d_in[13];
    const float* w2    = (const float*)d_in[14];
    const float* b2    = (const float*)d_in[15];
    const float* ln2_g = (const float*)d_in[16];
    const float* ln2_b = (const float*)d_in[17];
    const int*   amask = (const int*)d_in[18];
    const int*   gidx  = (const int*)d_in[20];

    int Lq = in_sizes[0] / (BSZ * DM);
    int Lv = in_sizes[1] / (BSZ * DM);
    int nv = in_sizes[20];
    int MKV = BSZ * Lv;

    float *pQ, *pK, *pV, *pCtx, *pT0, *pX, *pH;
    cudaGetSymbolAddress((void**)&pQ,   g_Q);
    cudaGetSymbolAddress((void**)&pK,   g_K);
    cudaGetSymbolAddress((void**)&pV,   g_V);
    cudaGetSymbolAddress((void**)&pCtx, g_ctx);
    cudaGetSymbolAddress((void**)&pT0,  g_t0);
    cudaGetSymbolAddress((void**)&pX,   g_x);
    cudaGetSymbolAddress((void**)&pH,   g_h);

    dim3 blk(256);
    // K, V projections over all predicate rows
    {
        dim3 grd(DM/64, (MKV + 63)/64);
        sgemm_nt<<<grd, blk>>>(pred, nullptr, w_ks, b_ks, pK, MKV, DM, DM, 0);
        sgemm_nt<<<grd, blk>>>(pred, nullptr, w_vs, b_vs, pV, MKV, DM, DM, 0);
    }
    // Q projection on gathered rows only
    {
        dim3 grd(DM/64, (nv + 63)/64);
        sgemm_nt<<<grd, blk>>>(ent, gidx, w_qs, b_qs, pQ, nv, DM, DM, 0);
    }
    // attention
    {
        dim3 grd(nv, NH);
        attn_kernel<<<grd, 128>>>(pQ, pK, pV, amask, gidx, pCtx, Lq, Lv);
    }
    // output projection + LN1 (residual = gathered entity rows)
    {
        dim3 grd(DM/64, (nv + 63)/64);
        sgemm_nt<<<grd, blk>>>(pCtx, nullptr, w_fc, b_fc, pT0, nv, DM, DM, 0);
        ln_res<<<nv, 128>>>(pT0, ent, gidx, ln1_g, ln1_b, pX);
    }
    // FFN
    {
        dim3 grd1(DI/64, (nv + 63)/64);
        sgemm_nt<<<grd1, blk>>>(pX, nullptr, w1, b1, pH, nv, DI, DM, 1);
        dim3 grd2(DM/64, (nv + 63)/64);
        sgemm_nt<<<grd2, blk>>>(pH, nullptr, w2, b2, pT0, nv, DM, DI, 0);
        ln_res<<<nv, 128>>>(pT0, pX, nullptr, ln2_g, ln2_b, (float*)d_out);
    }
}

// round 4
// speedup vs baseline: 1.0176x; 1.0176x over previous
#include <cuda_runtime.h>
#include <cuda_bf16.h>
#include <cstdint>
#include <math.h>

#define DM 512
#define DI 2048
#define NH 8
#define DKH 64
#define BSZ 32
#define MAXROWS (32*160)
#define MAXKV   (32*640)

// ---- scratch (device globals) ----
__device__ float g_Q  [MAXROWS*DM];   // padded B*Lq layout
__device__ float g_K  [MAXKV*DM];
__device__ float g_V  [MAXKV*DM];
__device__ float g_ctx[MAXROWS*DM];   // padded B*Lq layout
__device__ float g_t0 [MAXROWS*DM];
__device__ float g_x  [MAXROWS*DM];
__device__ float g_h  [MAXROWS*DI];

// ============================================================
// Tensor-core GEMM, emulated fp32 via bf16 hi/lo (3 mma passes).
// C[M,N] = A[M,K] @ W[N,K]^T + bias, optional relu, optional row
// gather on A. BM=BN=128, BK=32, 256 threads, warp tile 64x32.
// ============================================================
#define GBM 128
#define GBN 128
#define GBK 32
#define GLD 40   // padded K-stride in bf16 elems (80B: conflict-free ldmatrix)

__device__ __forceinline__ void ldsm_x4(unsigned* r, const void* p) {
    unsigned a = (unsigned)__cvta_generic_to_shared(p);
    asm volatile("ldmatrix.sync.aligned.m8n8.x4.shared.b16 {%0,%1,%2,%3}, [%4];"
        : "=r"(r[0]), "=r"(r[1]), "=r"(r[2]), "=r"(r[3]) : "r"(a));
}

__device__ __forceinline__ void ldsm_x2(unsigned* r, const void* p) {
    unsigned a = (unsigned)__cvta_generic_to_shared(p);
    asm volatile("ldmatrix.sync.aligned.m8n8.x2.shared.b16 {%0,%1}, [%2];"
        : "=r"(r[0]), "=r"(r[1]) : "r"(a));
}

__device__ __forceinline__ void mma16816(float* c, const unsigned* a, const unsigned* b) {
    asm volatile("mma.sync.aligned.m16n8k16.row.col.f32.bf16.bf16.f32 "
        "{%0,%1,%2,%3}, {%4,%5,%6,%7}, {%8,%9}, {%0,%1,%2,%3};"
        : "+f"(c[0]), "+f"(c[1]), "+f"(c[2]), "+f"(c[3])
        : "r"(a[0]), "r"(a[1]), "r"(a[2]), "r"(a[3]), "r"(b[0]), "r"(b[1]));
}

__global__ __launch_bounds__(256, 1)
void gemm_tc(const float* __restrict__ A, const int* __restrict__ rmap,
             const float* __restrict__ W, const float* __restrict__ bias,
             float* __restrict__ C, int M, int N, int K, int relu)
{
    __shared__ __nv_bfloat16 sAh[GBM][GLD];
    __shared__ __nv_bfloat16 sAl[GBM][GLD];
    __shared__ __nv_bfloat16 sBh[GBN][GLD];
    __shared__ __nv_bfloat16 sBl[GBN][GLD];

    const int tid  = threadIdx.x;
    const int lane = tid & 31;
    const int warp = tid >> 5;
    const int wm = warp >> 2;
    const int wn = warp & 3;           // 2 x 4 warp grid
    const int bm = blockIdx.y * GBM;
    const int bn = blockIdx.x * GBN;

    float acc[4][4][4];
    #pragma unroll
    for (int mi = 0; mi < 4; ++mi) {
        #pragma unroll
        for (int ni = 0; ni < 4; ++ni) {
            #pragma unroll
            for (int j = 0; j < 4; ++j) {
                acc[mi][ni][j] = 0.f;
            }
        }
    }

    for (int k0 = 0; k0 < K; k0 += GBK) {
        // ---- load + convert fp32 -> bf16 hi/lo ----
        #pragma unroll
        for (int i = 0; i < 4; ++i) {
            int idx = tid + i * 256;               // 0..1023
            int r  = idx >> 3;
            int c4 = (idx & 7) * 4;                // col start (of 4)
            float4 v = make_float4(0.f, 0.f, 0.f, 0.f);
            int ar = bm + r;
            if (ar < M) {
                int gr = rmap ? rmap[ar] : ar;
                v = *(const float4*)(A + (size_t)gr * K + k0 + c4);
            }
            float f0 = v.x, f1 = v.y, f2 = v.z, f3 = v.w;
            __nv_bfloat16 h0 = __float2bfloat16(f0);
            __nv_bfloat16 h1 = __float2bfloat16(f1);
            __nv_bfloat16 h2 = __float2bfloat16(f2);
            __nv_bfloat16 h3 = __float2bfloat16(f3);
            sAh[r][c4+0] = h0; sAh[r][c4+1] = h1; sAh[r][c4+2] = h2; sAh[r][c4+3] = h3;
            sAl[r][c4+0] = __float2bfloat16(f0 - __bfloat162float(h0));
            sAl[r][c4+1] = __float2bfloat16(f1 - __bfloat162float(h1));
            sAl[r][c4+2] = __float2bfloat16(f2 - __bfloat162float(h2));
            sAl[r][c4+3] = __float2bfloat16(f3 - __bfloat162float(h3));

            float4 w = make_float4(0.f, 0.f, 0.f, 0.f);
            int wr = bn + r;
            if (wr < N) {
                w = *(const float4*)(W + (size_t)wr * K + k0 + c4);
            }
            float g0 = w.x, g1 = w.y, g2 = w.z, g3 = w.w;
            __nv_bfloat16 e0 = __float2bfloat16(g0);
            __nv_bfloat16 e1 = __float2bfloat16(g1);
            __nv_bfloat16 e2 = __float2bfloat16(g2);
            __nv_bfloat16 e3 = __float2bfloat16(g3);
            sBh[r][c4+0] = e0; sBh[r][c4+1] = e1; sBh[r][c4+2] = e2; sBh[r][c4+3] = e3;
            sBl[r][c4+0] = __float2bfloat16(g0 - __bfloat162float(e0));
            sBl[r][c4+1] = __float2bfloat16(g1 - __bfloat162float(e1));
            sBl[r][c4+2] = __float2bfloat16(g2 - __bfloat162float(e2));
            sBl[r][c4+3] = __float2bfloat16(g3 - __bfloat162float(e3));
        }
        __syncthreads();

        #pragma unroll
        for (int ks = 0; ks < 2; ++ks) {
            const int kk = ks * 16;
            unsigned ah[4][4], al[4][4], bh[4][2], bl[4][2];
            const int lr = lane & 15;
            const int lk = (lane >> 4) * 8;
            #pragma unroll
            for (int mi = 0; mi < 4; ++mi) {
                ldsm_x4(ah[mi], &sAh[wm * 64 + mi * 16 + lr][kk + lk]);
                ldsm_x4(al[mi], &sAl[wm * 64 + mi * 16 + lr][kk + lk]);
            }
            const int l8  = lane & 7;
            const int lk2 = ((lane >> 3) & 1) * 8;
            #pragma unroll
            for (int ni = 0; ni < 4; ++ni) {
                ldsm_x2(bh[ni], &sBh[wn * 32 + ni * 8 + l8][kk + lk2]);
                ldsm_x2(bl[ni], &sBl[wn * 32 + ni * 8 + l8][kk + lk2]);
            }
            #pragma unroll
            for (int mi = 0; mi < 4; ++mi) {
                #pragma unroll
                for (int ni = 0; ni < 4; ++ni) {
                    mma16816(acc[mi][ni], ah[mi], bh[ni]);
                    mma16816(acc[mi][ni], ah[mi], bl[ni]);
                    mma16816(acc[mi][ni], al[mi], bh[ni]);
                }
            }
        }
        __syncthreads();
    }

    // ---- epilogue ----
    #pragma unroll
    for (int mi = 0; mi < 4; ++mi) {
        int r0 = bm + wm * 64 + mi * 16 + (lane >> 2);
        #pragma unroll
        for (int ni = 0; ni < 4; ++ni) {
            int c = bn + wn * 32 + ni * 8 + (lane & 3) * 2;
            float b0 = bias[c];
            float b1 = bias[c + 1];
            float v0 = acc[mi][ni][0] + b0;
            float v1 = acc[mi][ni][1] + b1;
            float v2 = acc[mi][ni][2] + b0;
            float v3 = acc[mi][ni][3] + b1;
            if (relu) {
                v0 = fmaxf(v0, 0.f); v1 = fmaxf(v1, 0.f);
                v2 = fmaxf(v2, 0.f); v3 = fmaxf(v3, 0.f);
            }
            if (r0 < M) {
                *(float2*)(C + (size_t)r0 * N + c) = make_float2(v0, v1);
            }
            if (r0 + 8 < M) {
                *(float2*)(C + (size_t)(r0 + 8) * N + c) = make_float2(v2, v3);
            }
        }
    }
}

// ============================================================
// LayerNorm with residual: out[row] = LN(A[row] + R[rmap?rmap[row]:row])
// ============================================================
__global__ void ln_res(const float* __restrict__ A, const float* __restrict__ R,
                       const int* __restrict__ rmap,
                       const float* __restrict__ g, const float* __restrict__ beta,
                       float* __restrict__ out)
{
    int row = blockIdx.x;
    int tid = threadIdx.x;   // 128
    __shared__ float red [128];
    __shared__ float red2[128];
    int rrow = rmap ? rmap[row] : row;
    float4 x = ((const float4*)(A + (size_t)row*DM))[tid];
    float4 r = ((const float4*)(R + (size_t)rrow*DM))[tid];
    x.x += r.x; x.y += r.y; x.z += r.z; x.w += r.w;
    red [tid] = x.x + x.y + x.z + x.w;
    red2[tid] = x.x*x.x + x.y*x.y + x.z*x.z + x.w*x.w;
    __syncthreads();
    #pragma unroll
    for (int o = 64; o > 0; o >>= 1) {
        if (tid < o) { red[tid] += red[tid+o]; red2[tid] += red2[tid+o]; }
        __syncthreads();
    }
    float mean = red[0] * (1.f/512.f);
    float var  = red2[0] * (1.f/512.f) - mean*mean;
    float inv  = rsqrtf(var + 1e-5f);
    float4 gg = ((const float4*)g)[tid];
    float4 bb = ((const float4*)beta)[tid];
    float4 o4;
    o4.x = (x.x - mean)*inv*gg.x + bb.x;
    o4.y = (x.y - mean)*inv*gg.y + bb.y;
    o4.z = (x.z - mean)*inv*gg.z + bb.z;
    o4.w = (x.w - mean)*inv*gg.w + bb.w;
    ((float4*)(out + (size_t)row*DM))[tid] = o4;
}

// ============================================================
// Flash-style attention: block = (16-query tile, head, batch).
// K/V streamed in 32-key tiles through smem, online softmax.
// Q/ctx in padded B*Lq layout. 128 threads: thread = (tq 0..15, kc 0..7).
// ============================================================
__global__ __launch_bounds__(128, 8)
void attn_flash(const float* __restrict__ Q, const float* __restrict__ Kb,
                const float* __restrict__ Vb, const int* __restrict__ mask,
                float* __restrict__ ctx, int Lq, int Lv)
{
    const int qt = blockIdx.x;
    const int h  = blockIdx.y;
    const int b  = blockIdx.z;
    const int t  = threadIdx.x;
    const int tq = t >> 3;          // query within tile
    const int kc = t & 7;           // key group / dim group
    const int q  = qt * 16 + tq;
    const bool qvalid = q < Lq;
    const int d0 = kc * 8;

    __shared__ float sQ[16][68];
    __shared__ float sK[32][68];
    __shared__ float sV[32][68];
    __shared__ float sP[16][36];

    // load Q tile (16 x 64)
    #pragma unroll
    for (int i = 0; i < 2; ++i) {
        int idx = t + i * 128;
        int r  = idx >> 4;
        int c4 = idx & 15;
        int qq = qt * 16 + r;
        float4 v = make_float4(0.f, 0.f, 0.f, 0.f);
        if (qq < Lq) {
            v = *(const float4*)(Q + ((size_t)(b * Lq + qq)) * DM + h * DKH + c4 * 4);
        }
        *(float4*)&sQ[r][c4 * 4] = v;
    }

    float acc[8] = {0.f, 0.f, 0.f, 0.f, 0.f, 0.f, 0.f, 0.f};
    float m_run = -INFINITY;
    float l_run = 0.f;
    const int* mrow = mask + ((size_t)(b * Lq + (qvalid ? q : 0))) * Lv;

    for (int kv0 = 0; kv0 < Lv; kv0 += 32) {
        __syncthreads();   // covers Q store (first iter) & previous tile use
        #pragma unroll
        for (int i = 0; i < 4; ++i) {
            int idx = t + i * 128;
            int r  = idx >> 4;
            int c4 = idx & 15;
            int kv = kv0 + r;
            float4 kvv = make_float4(0.f, 0.f, 0.f, 0.f);
            float4 vvv = make_float4(0.f, 0.f, 0.f, 0.f);
            if (kv < Lv) {
                size_t base = ((size_t)(b * Lv + kv)) * DM + h * DKH + c4 * 4;
                kvv = *(const float4*)(Kb + base);
                vvv = *(const float4*)(Vb + base);
            }
            *(float4*)&sK[r][c4 * 4] = kvv;
            *(float4*)&sV[r][c4 * 4] = vvv;
        }
        __syncthreads();

        // scores: 4 keys per thread
        float s[4];
        #pragma unroll
        for (int c = 0; c < 4; ++c) {
            int k  = kc * 4 + c;
            int kv = kv0 + k;
            bool msk = true;
            if (qvalid && kv < Lv) {
                msk = (mrow[kv] != 0);
            }
            float a = 0.f;
            #pragma unroll
            for (int d4 = 0; d4 < 16; ++d4) {
                float4 qv = *(const float4*)&sQ[tq][d4 * 4];
                float4 kk = *(const float4*)&sK[k][d4 * 4];
                a += qv.x*kk.x + qv.y*kk.y + qv.z*kk.z + qv.w*kk.w;
            }
            s[c] = msk ? -INFINITY : a * 0.125f;
        }
        float tm = fmaxf(fmaxf(s[0], s[1]), fmaxf(s[2], s[3]));
        tm = fmaxf(tm, __shfl_xor_sync(0xffffffffu, tm, 1));
        tm = fmaxf(tm, __shfl_xor_sync(0xffffffffu, tm, 2));
        tm = fmaxf(tm, __shfl_xor_sync(0xffffffffu, tm, 4));
        float newm  = fmaxf(m_run, tm);
        float scale = __expf(fminf(m_run - newm, 0.f));  // -inf-(-inf)=nan -> fminf->0 -> scale 1
        float ts = 0.f;
        #pragma unroll
        for (int c = 0; c < 4; ++c) {
            float p = (s[c] == -INFINITY) ? 0.f : __expf(s[c] - newm);
            sP[tq][kc * 4 + c] = p;
            ts += p;
        }
        ts += __shfl_xor_sync(0xffffffffu, ts, 1);
        ts += __shfl_xor_sync(0xffffffffu, ts, 2);
        ts += __shfl_xor_sync(0xffffffffu, ts, 4);
        l_run = l_run * scale + ts;
        m_run = newm;
        #pragma unroll
        for (int j = 0; j < 8; ++j) {
            acc[j] *= scale;
        }
        __syncwarp();

        // PV accumulate: 8 output dims per thread
        #pragma unroll 8
        for (int k = 0; k < 32; ++k) {
            float p = sP[tq][k];
            float4 v0 = *(const float4*)&sV[k][d0];
            float4 v1 = *(const float4*)&sV[k][d0 + 4];
            acc[0] += p * v0.x; acc[1] += p * v0.y; acc[2] += p * v0.z; acc[3] += p * v0.w;
            acc[4] += p * v1.x; acc[5] += p * v1.y; acc[6] += p * v1.z; acc[7] += p * v1.w;
        }
    }

    if (qvalid) {
        float inv = 1.f / l_run;
        float* op = ctx + ((size_t)(b * Lq + q)) * DM + h * DKH + d0;
        *(float4*)op       = make_float4(acc[0]*inv, acc[1]*inv, acc[2]*inv, acc[3]*inv);
        *(float4*)(op + 4) = make_float4(acc[4]*inv, acc[5]*inv, acc[6]*inv, acc[7]*inv);
    }
}

// ============================================================
// launcher
// ============================================================
extern "C" void kernel_launch(void* const* d_in, const int* in_sizes, int n_in,
                              void* d_out, int out_size)
{
    const float* ent   = (const float*)d_in[0];
    const float* pred  = (const float*)d_in[1];
    const float* w_qs  = (const float*)d_in[2];
    const float* b_qs  = (const float*)d_in[3];
    const float* w_ks  = (const float*)d_in[4];
    const float* b_ks  = (const float*)d_in[5];
    const float* w_vs  = (const float*)d_in[6];
    const float* b_vs  = (const float*)d_in[7];
    const float* w_fc  = (const float*)d_in[8];
    const float* b_fc  = (const float*)d_in[9];
    const float* ln1_g = (const float*)d_in[10];
    const float* ln1_b = (const float*)d_in[11];
    const float* w1    = (const float*)d_in[12];
    const float* b1    = (const float*)d_in[13];
    const float* w2    = (const float*)d_in[14];
    const float* b2    = (const float*)d_in[15];
    const float* ln2_g = (const float*)d_in[16];
    const float* ln2_b = (const float*)d_in[17];
    const int*   amask = (const int*)d_in[18];
    const int*   gidx  = (const int*)d_in[20];

    int Lq  = in_sizes[0] / (BSZ * DM);
    int Lv  = in_sizes[1] / (BSZ * DM);
    int nv  = in_sizes[20];
    int MKV = BSZ * Lv;
    int MQ  = BSZ * Lq;

    float *pQ, *pK, *pV, *pCtx, *pT0, *pX, *pH;
    cudaGetSymbolAddress((void**)&pQ,   g_Q);
    cudaGetSymbolAddress((void**)&pK,   g_K);
    cudaGetSymbolAddress((void**)&pV,   g_V);
    cudaGetSymbolAddress((void**)&pCtx, g_ctx);
    cudaGetSymbolAddress((void**)&pT0,  g_t0);
    cudaGetSymbolAddress((void**)&pX,   g_x);
    cudaGetSymbolAddress((void**)&pH,   g_h);

    dim3 blk(256);
    // K, V projections (all predicate rows)
    {
        dim3 grd(DM / GBN, (MKV + GBM - 1) / GBM);
        gemm_tc<<<grd, blk>>>(pred, nullptr, w_ks, b_ks, pK, MKV, DM, DM, 0);
        gemm_tc<<<grd, blk>>>(pred, nullptr, w_vs, b_vs, pV, MKV, DM, DM, 0);
    }
    // Q projection, padded layout (all B*Lq rows)
    {
        dim3 grd(DM / GBN, (MQ + GBM - 1) / GBM);
        gemm_tc<<<grd, blk>>>(ent, nullptr, w_qs, b_qs, pQ, MQ, DM, DM, 0);
    }
    // attention (padded ctx)
    {
        dim3 grd((Lq + 15) / 16, NH, BSZ);
        attn_flash<<<grd, 128>>>(pQ, pK, pV, amask, pCtx, Lq, Lv);
    }
    // output projection (gathers valid rows) + LN1
    {
        dim3 grd(DM / GBN, (nv + GBM - 1) / GBM);
        gemm_tc<<<grd, blk>>>(pCtx, gidx, w_fc, b_fc, pT0, nv, DM, DM, 0);
        ln_res<<<nv, 128>>>(pT0, ent, gidx, ln1_g, ln1_b, pX);
    }
    // FFN
    {
        dim3 grd1(DI / GBN, (nv + GBM - 1) / GBM);
        gemm_tc<<<grd1, blk>>>(pX, nullptr, w1, b1, pH, nv, DI, DM, 1);
        dim3 grd2(DM / GBN, (nv + GBM - 1) / GBM);
        gemm_tc<<<grd2, blk>>>(pH, nullptr, w2, b2, pT0, nv, DM, DI, 0);
        ln_res<<<nv, 128>>>(pT0, pX, nullptr, ln2_g, ln2_b, (float*)d_out);
    }
}

// round 5
// speedup vs baseline: 1.0324x; 1.0145x over previous
#include <cuda_runtime.h>
#include <cuda_bf16.h>
#include <cstdint>
#include <math.h>

#define DM 512
#define DI 2048
#define NH 8
#define DKH 64
#define BSZ 32
#define MAXROWS (32*160)
#define MAXKV   (32*640)

// ---- fp32 scratch ----
__device__ float g_Q  [MAXROWS*DM];   // padded B*Lq layout
__device__ float g_K  [MAXKV*DM];
__device__ float g_V  [MAXKV*DM];
__device__ float g_t0 [MAXROWS*DM];
__device__ float g_x  [MAXROWS*DM];

// ---- bf16 hi/lo scratch ----
__device__ __nv_bfloat16 g_predH[MAXKV*DM],   g_predL[MAXKV*DM];
__device__ __nv_bfloat16 g_entH [MAXROWS*DM], g_entL [MAXROWS*DM];
__device__ __nv_bfloat16 g_ctxH [MAXROWS*DM], g_ctxL [MAXROWS*DM];
__device__ __nv_bfloat16 g_xH   [MAXROWS*DM], g_xL   [MAXROWS*DM];
__device__ __nv_bfloat16 g_hH   [MAXROWS*DI], g_hL   [MAXROWS*DI];
__device__ __nv_bfloat16 g_wqH[DM*DM], g_wqL[DM*DM];
__device__ __nv_bfloat16 g_wkH[DM*DM], g_wkL[DM*DM];
__device__ __nv_bfloat16 g_wvH[DM*DM], g_wvL[DM*DM];
__device__ __nv_bfloat16 g_wfH[DM*DM], g_wfL[DM*DM];
__device__ __nv_bfloat16 g_w1H[DI*DM], g_w1L[DI*DM];
__device__ __nv_bfloat16 g_w2H[DM*DI], g_w2L[DM*DI];

__device__ __forceinline__ unsigned pack_bf2(float a, float b) {
    __nv_bfloat162 t = __floats2bfloat162_rn(a, b);
    return *(unsigned*)&t;
}

// ============================================================
// fp32 -> bf16 hi/lo conversion (elementwise, x4 vectorized)
// ============================================================
__global__ void cvt_hl(const float* __restrict__ in,
                       __nv_bfloat16* __restrict__ hi,
                       __nv_bfloat16* __restrict__ lo, int n4)
{
    int i = blockIdx.x * blockDim.x + threadIdx.x;
    if (i >= n4) return;
    float4 v = ((const float4*)in)[i];
    float h0 = __bfloat162float(__float2bfloat16(v.x));
    float h1 = __bfloat162float(__float2bfloat16(v.y));
    float h2 = __bfloat162float(__float2bfloat16(v.z));
    float h3 = __bfloat162float(__float2bfloat16(v.w));
    uint2 uh, ul;
    uh.x = pack_bf2(v.x, v.y);
    uh.y = pack_bf2(v.z, v.w);
    ul.x = pack_bf2(v.x - h0, v.y - h1);
    ul.y = pack_bf2(v.z - h2, v.w - h3);
    *(uint2*)(hi + 4 * (size_t)i) = uh;
    *(uint2*)(lo + 4 * (size_t)i) = ul;
}

// ============================================================
// Tensor-core GEMM on precomputed bf16 hi/lo operands.
// C = A @ W^T + bias. Output fp32 (Cf) and/or bf16 hi/lo (Ch,Cl).
// BM=BN=128, BK=32, 256 threads, warp tile 64x32, 3 mma passes.
// ============================================================
#define GBM 128
#define GBN 128
#define GBK 32
#define GLD 40   // padded K-stride (80B rows: conflict-free ldmatrix)

__device__ __forceinline__ void ldsm_x4(unsigned* r, const void* p) {
    unsigned a = (unsigned)__cvta_generic_to_shared(p);
    asm volatile("ldmatrix.sync.aligned.m8n8.x4.shared.b16 {%0,%1,%2,%3}, [%4];"
        : "=r"(r[0]), "=r"(r[1]), "=r"(r[2]), "=r"(r[3]) : "r"(a));
}

__device__ __forceinline__ void ldsm_x2(unsigned* r, const void* p) {
    unsigned a = (unsigned)__cvta_generic_to_shared(p);
    asm volatile("ldmatrix.sync.aligned.m8n8.x2.shared.b16 {%0,%1}, [%2];"
        : "=r"(r[0]), "=r"(r[1]) : "r"(a));
}

__device__ __forceinline__ void mma16816(float* c, const unsigned* a, const unsigned* b) {
    asm volatile("mma.sync.aligned.m16n8k16.row.col.f32.bf16.bf16.f32 "
        "{%0,%1,%2,%3}, {%4,%5,%6,%7}, {%8,%9}, {%0,%1,%2,%3};"
        : "+f"(c[0]), "+f"(c[1]), "+f"(c[2]), "+f"(c[3])
        : "r"(a[0]), "r"(a[1]), "r"(a[2]), "r"(a[3]), "r"(b[0]), "r"(b[1]));
}

__global__ __launch_bounds__(256, 2)
void gemm_hl(const __nv_bfloat16* __restrict__ Ah, const __nv_bfloat16* __restrict__ Al,
             const int* __restrict__ rmap,
             const __nv_bfloat16* __restrict__ Wh, const __nv_bfloat16* __restrict__ Wl,
             const float* __restrict__ bias,
             float* __restrict__ Cf,
             __nv_bfloat16* __restrict__ Ch, __nv_bfloat16* __restrict__ Cl,
             int M, int N, int K, int relu)
{
    __shared__ __nv_bfloat16 s[4][GBM][GLD];   // 0=Ah 1=Al 2=Wh 3=Wl

    const int tid  = threadIdx.x;
    const int lane = tid & 31;
    const int warp = tid >> 5;
    const int wm = warp >> 2;
    const int wn = warp & 3;
    const int bm = blockIdx.y * GBM;
    const int bn = blockIdx.x * GBN;

    float acc[4][4][4];
    #pragma unroll
    for (int mi = 0; mi < 4; ++mi) {
        #pragma unroll
        for (int ni = 0; ni < 4; ++ni) {
            #pragma unroll
            for (int j = 0; j < 4; ++j) acc[mi][ni][j] = 0.f;
        }
    }

    for (int k0 = 0; k0 < K; k0 += GBK) {
        // ---- fill 4 tiles (uint2 = 4 bf16 per chunk; 16 chunks/thread) ----
        #pragma unroll
        for (int i = 0; i < 16; ++i) {
            int idx = tid + i * 256;      // 0..4095
            int buf = idx >> 10;
            int j   = idx & 1023;
            int r   = j >> 3;
            int c4  = (j & 7) * 4;
            const __nv_bfloat16* src;
            int grow;
            if (buf < 2) {
                int ar = bm + r;
                grow = (ar < M) ? (rmap ? rmap[ar] : ar) : -1;
                src = (buf == 1) ? Al : Ah;
            } else {
                int wr = bn + r;
                grow = (wr < N) ? wr : -1;
                src = (buf == 3) ? Wl : Wh;
            }
            uint2 v = make_uint2(0u, 0u);
            if (grow >= 0) {
                v = *(const uint2*)(src + (size_t)grow * K + k0 + c4);
            }
            *(uint2*)&s[buf][r][c4] = v;
        }
        __syncthreads();

        #pragma unroll
        for (int ks = 0; ks < 2; ++ks) {
            const int kk = ks * 16;
            unsigned ah[4][4], al[4][4], bh[4][2], bl[4][2];
            const int lr = lane & 15;
            const int lk = (lane >> 4) * 8;
            #pragma unroll
            for (int mi = 0; mi < 4; ++mi) {
                ldsm_x4(ah[mi], &s[0][wm * 64 + mi * 16 + lr][kk + lk]);
                ldsm_x4(al[mi], &s[1][wm * 64 + mi * 16 + lr][kk + lk]);
            }
            const int l8  = lane & 7;
            const int lk2 = ((lane >> 3) & 1) * 8;
            #pragma unroll
            for (int ni = 0; ni < 4; ++ni) {
                ldsm_x2(bh[ni], &s[2][wn * 32 + ni * 8 + l8][kk + lk2]);
                ldsm_x2(bl[ni], &s[3][wn * 32 + ni * 8 + l8][kk + lk2]);
            }
            #pragma unroll
            for (int mi = 0; mi < 4; ++mi) {
                #pragma unroll
                for (int ni = 0; ni < 4; ++ni) {
                    mma16816(acc[mi][ni], ah[mi], bh[ni]);
                    mma16816(acc[mi][ni], ah[mi], bl[ni]);
                    mma16816(acc[mi][ni], al[mi], bh[ni]);
                }
            }
        }
        __syncthreads();
    }

    // ---- epilogue ----
    #pragma unroll
    for (int mi = 0; mi < 4; ++mi) {
        int r0 = bm + wm * 64 + mi * 16 + (lane >> 2);
        #pragma unroll
        for (int ni = 0; ni < 4; ++ni) {
            int c = bn + wn * 32 + ni * 8 + (lane & 3) * 2;
            float b0 = bias[c];
            float b1 = bias[c + 1];
            float v0 = acc[mi][ni][0] + b0;
            float v1 = acc[mi][ni][1] + b1;
            float v2 = acc[mi][ni][2] + b0;
            float v3 = acc[mi][ni][3] + b1;
            if (relu) {
                v0 = fmaxf(v0, 0.f); v1 = fmaxf(v1, 0.f);
                v2 = fmaxf(v2, 0.f); v3 = fmaxf(v3, 0.f);
            }
            if (Cf) {
                if (r0 < M)     *(float2*)(Cf + (size_t)r0 * N + c)       = make_float2(v0, v1);
                if (r0 + 8 < M) *(float2*)(Cf + (size_t)(r0 + 8) * N + c) = make_float2(v2, v3);
            }
            if (Ch) {
                if (r0 < M) {
                    size_t o = (size_t)r0 * N + c;
                    float h0 = __bfloat162float(__float2bfloat16(v0));
                    float h1 = __bfloat162float(__float2bfloat16(v1));
                    *(unsigned*)(Ch + o) = pack_bf2(v0, v1);
                    *(unsigned*)(Cl + o) = pack_bf2(v0 - h0, v1 - h1);
                }
                if (r0 + 8 < M) {
                    size_t o = (size_t)(r0 + 8) * N + c;
                    float h2 = __bfloat162float(__float2bfloat16(v2));
                    float h3 = __bfloat162float(__float2bfloat16(v3));
                    *(unsigned*)(Ch + o) = pack_bf2(v2, v3);
                    *(unsigned*)(Cl + o) = pack_bf2(v2 - h2, v3 - h3);
                }
            }
        }
    }
}

// ============================================================
// LayerNorm with residual; optional bf16 hi/lo secondary output.
// ============================================================
__global__ void ln_res(const float* __restrict__ A, const float* __restrict__ R,
                       const int* __restrict__ rmap,
                       const float* __restrict__ g, const float* __restrict__ beta,
                       float* __restrict__ out,
                       __nv_bfloat16* __restrict__ outH, __nv_bfloat16* __restrict__ outL)
{
    int row = blockIdx.x;
    int tid = threadIdx.x;   // 128
    __shared__ float red [128];
    __shared__ float red2[128];
    int rrow = rmap ? rmap[row] : row;
    float4 x = ((const float4*)(A + (size_t)row*DM))[tid];
    float4 r = ((const float4*)(R + (size_t)rrow*DM))[tid];
    x.x += r.x; x.y += r.y; x.z += r.z; x.w += r.w;
    red [tid] = x.x + x.y + x.z + x.w;
    red2[tid] = x.x*x.x + x.y*x.y + x.z*x.z + x.w*x.w;
    __syncthreads();
    #pragma unroll
    for (int o = 64; o > 0; o >>= 1) {
        if (tid < o) { red[tid] += red[tid+o]; red2[tid] += red2[tid+o]; }
        __syncthreads();
    }
    float mean = red[0] * (1.f/512.f);
    float var  = red2[0] * (1.f/512.f) - mean*mean;
    float inv  = rsqrtf(var + 1e-5f);
    float4 gg = ((const float4*)g)[tid];
    float4 bb = ((const float4*)beta)[tid];
    float4 o4;
    o4.x = (x.x - mean)*inv*gg.x + bb.x;
    o4.y = (x.y - mean)*inv*gg.y + bb.y;
    o4.z = (x.z - mean)*inv*gg.z + bb.z;
    o4.w = (x.w - mean)*inv*gg.w + bb.w;
    ((float4*)(out + (size_t)row*DM))[tid] = o4;
    if (outH) {
        size_t o = (size_t)row * DM + tid * 4;
        float h0 = __bfloat162float(__float2bfloat16(o4.x));
        float h1 = __bfloat162float(__float2bfloat16(o4.y));
        float h2 = __bfloat162float(__float2bfloat16(o4.z));
        float h3 = __bfloat162float(__float2bfloat16(o4.w));
        uint2 uh, ul;
        uh.x = pack_bf2(o4.x, o4.y);
        uh.y = pack_bf2(o4.z, o4.w);
        ul.x = pack_bf2(o4.x - h0, o4.y - h1);
        ul.y = pack_bf2(o4.z - h2, o4.w - h3);
        *(uint2*)(outH + o) = uh;
        *(uint2*)(outL + o) = ul;
    }
}

// ============================================================
// Flash-style attention; writes ctx directly as bf16 hi/lo.
// ============================================================
__global__ __launch_bounds__(128, 8)
void attn_flash(const float* __restrict__ Q, const float* __restrict__ Kb,
                const float* __restrict__ Vb, const int* __restrict__ mask,
                __nv_bfloat16* __restrict__ ctxH, __nv_bfloat16* __restrict__ ctxL,
                int Lq, int Lv)
{
    const int qt = blockIdx.x;
    const int h  = blockIdx.y;
    const int b  = blockIdx.z;
    const int t  = threadIdx.x;
    const int tq = t >> 3;
    const int kc = t & 7;
    const int q  = qt * 16 + tq;
    const bool qvalid = q < Lq;
    const int d0 = kc * 8;

    __shared__ float sQ[16][68];
    __shared__ float sK[32][68];
    __shared__ float sV[32][68];
    __shared__ float sP[16][36];

    #pragma unroll
    for (int i = 0; i < 2; ++i) {
        int idx = t + i * 128;
        int r  = idx >> 4;
        int c4 = idx & 15;
        int qq = qt * 16 + r;
        float4 v = make_float4(0.f, 0.f, 0.f, 0.f);
        if (qq < Lq) {
            v = *(const float4*)(Q + ((size_t)(b * Lq + qq)) * DM + h * DKH + c4 * 4);
        }
        *(float4*)&sQ[r][c4 * 4] = v;
    }

    float acc[8] = {0.f, 0.f, 0.f, 0.f, 0.f, 0.f, 0.f, 0.f};
    float m_run = -INFINITY;
    float l_run = 0.f;
    const int* mrow = mask + ((size_t)(b * Lq + (qvalid ? q : 0))) * Lv;

    for (int kv0 = 0; kv0 < Lv; kv0 += 32) {
        __syncthreads();
        #pragma unroll
        for (int i = 0; i < 4; ++i) {
            int idx = t + i * 128;
            int r  = idx >> 4;
            int c4 = idx & 15;
            int kv = kv0 + r;
            float4 kvv = make_float4(0.f, 0.f, 0.f, 0.f);
            float4 vvv = make_float4(0.f, 0.f, 0.f, 0.f);
            if (kv < Lv) {
                size_t base = ((size_t)(b * Lv + kv)) * DM + h * DKH + c4 * 4;
                kvv = *(const float4*)(Kb + base);
                vvv = *(const float4*)(Vb + base);
            }
            *(float4*)&sK[r][c4 * 4] = kvv;
            *(float4*)&sV[r][c4 * 4] = vvv;
        }
        __syncthreads();

        float s[4];
        #pragma unroll
        for (int c = 0; c < 4; ++c) {
            int k  = kc * 4 + c;
            int kv = kv0 + k;
            bool msk = true;
            if (qvalid && kv < Lv) {
                msk = (mrow[kv] != 0);
            }
            float a = 0.f;
            #pragma unroll
            for (int d4 = 0; d4 < 16; ++d4) {
                float4 qv = *(const float4*)&sQ[tq][d4 * 4];
                float4 kk = *(const float4*)&sK[k][d4 * 4];
                a += qv.x*kk.x + qv.y*kk.y + qv.z*kk.z + qv.w*kk.w;
            }
            s[c] = msk ? -INFINITY : a * 0.125f;
        }
        float tm = fmaxf(fmaxf(s[0], s[1]), fmaxf(s[2], s[3]));
        tm = fmaxf(tm, __shfl_xor_sync(0xffffffffu, tm, 1));
        tm = fmaxf(tm, __shfl_xor_sync(0xffffffffu, tm, 2));
        tm = fmaxf(tm, __shfl_xor_sync(0xffffffffu, tm, 4));
        float newm  = fmaxf(m_run, tm);
        float scale = __expf(fminf(m_run - newm, 0.f));
        float ts = 0.f;
        #pragma unroll
        for (int c = 0; c < 4; ++c) {
            float p = (s[c] == -INFINITY) ? 0.f : __expf(s[c] - newm);
            sP[tq][kc * 4 + c] = p;
            ts += p;
        }
        ts += __shfl_xor_sync(0xffffffffu, ts, 1);
        ts += __shfl_xor_sync(0xffffffffu, ts, 2);
        ts += __shfl_xor_sync(0xffffffffu, ts, 4);
        l_run = l_run * scale + ts;
        m_run = newm;
        #pragma unroll
        for (int j = 0; j < 8; ++j) acc[j] *= scale;
        __syncwarp();

        #pragma unroll 8
        for (int k = 0; k < 32; ++k) {
            float p = sP[tq][k];
            float4 v0 = *(const float4*)&sV[k][d0];
            float4 v1 = *(const float4*)&sV[k][d0 + 4];
            acc[0] += p * v0.x; acc[1] += p * v0.y; acc[2] += p * v0.z; acc[3] += p * v0.w;
            acc[4] += p * v1.x; acc[5] += p * v1.y; acc[6] += p * v1.z; acc[7] += p * v1.w;
        }
    }

    if (qvalid) {
        float inv = 1.f / l_run;
        float o[8];
        #pragma unroll
        for (int j = 0; j < 8; ++j) o[j] = acc[j] * inv;
        size_t off = ((size_t)(b * Lq + q)) * DM + h * DKH + d0;
        uint4 uh, ul;
        uh.x = pack_bf2(o[0], o[1]); uh.y = pack_bf2(o[2], o[3]);
        uh.z = pack_bf2(o[4], o[5]); uh.w = pack_bf2(o[6], o[7]);
        float hh[8];
        #pragma unroll
        for (int j = 0; j < 8; ++j) hh[j] = __bfloat162float(__float2bfloat16(o[j]));
        ul.x = pack_bf2(o[0]-hh[0], o[1]-hh[1]); ul.y = pack_bf2(o[2]-hh[2], o[3]-hh[3]);
        ul.z = pack_bf2(o[4]-hh[4], o[5]-hh[5]); ul.w = pack_bf2(o[6]-hh[6], o[7]-hh[7]);
        *(uint4*)(ctxH + off) = uh;
        *(uint4*)(ctxL + off) = ul;
    }
}

// ============================================================
// launcher
// ============================================================
extern "C" void kernel_launch(void* const* d_in, const int* in_sizes, int n_in,
                              void* d_out, int out_size)
{
    const float* ent   = (const float*)d_in[0];
    const float* pred  = (const float*)d_in[1];
    const float* w_qs  = (const float*)d_in[2];
    const float* b_qs  = (const float*)d_in[3];
    const float* w_ks  = (const float*)d_in[4];
    const float* b_ks  = (const float*)d_in[5];
    const float* w_vs  = (const float*)d_in[6];
    const float* b_vs  = (const float*)d_in[7];
    const float* w_fc  = (const float*)d_in[8];
    const float* b_fc  = (const float*)d_in[9];
    const float* ln1_g = (const float*)d_in[10];
    const float* ln1_b = (const float*)d_in[11];
    const float* w1    = (const float*)d_in[12];
    const float* b1    = (const float*)d_in[13];
    const float* w2    = (const float*)d_in[14];
    const float* b2    = (const float*)d_in[15];
    const float* ln2_g = (const float*)d_in[16];
    const float* ln2_b = (const float*)d_in[17];
    const int*   amask = (const int*)d_in[18];
    const int*   gidx  = (const int*)d_in[20];

    int Lq  = in_sizes[0] / (BSZ * DM);
    int Lv  = in_sizes[1] / (BSZ * DM);
    int nv  = in_sizes[20];
    int MKV = BSZ * Lv;
    int MQ  = BSZ * Lq;

    float *pQ, *pK, *pV, *pT0, *pX;
    cudaGetSymbolAddress((void**)&pQ,  g_Q);
    cudaGetSymbolAddress((void**)&pK,  g_K);
    cudaGetSymbolAddress((void**)&pV,  g_V);
    cudaGetSymbolAddress((void**)&pT0, g_t0);
    cudaGetSymbolAddress((void**)&pX,  g_x);

    __nv_bfloat16 *predH,*predL,*entH,*entL,*ctxH,*ctxL,*xH,*xL,*hH,*hL;
    __nv_bfloat16 *wqH,*wqL,*wkH,*wkL,*wvH,*wvL,*wfH,*wfL,*w1H,*w1L,*w2H,*w2L;
    cudaGetSymbolAddress((void**)&predH, g_predH); cudaGetSymbolAddress((void**)&predL, g_predL);
    cudaGetSymbolAddress((void**)&entH,  g_entH);  cudaGetSymbolAddress((void**)&entL,  g_entL);
    cudaGetSymbolAddress((void**)&ctxH,  g_ctxH);  cudaGetSymbolAddress((void**)&ctxL,  g_ctxL);
    cudaGetSymbolAddress((void**)&xH,    g_xH);    cudaGetSymbolAddress((void**)&xL,    g_xL);
    cudaGetSymbolAddress((void**)&hH,    g_hH);    cudaGetSymbolAddress((void**)&hL,    g_hL);
    cudaGetSymbolAddress((void**)&wqH,   g_wqH);   cudaGetSymbolAddress((void**)&wqL,   g_wqL);
    cudaGetSymbolAddress((void**)&wkH,   g_wkH);   cudaGetSymbolAddress((void**)&wkL,   g_wkL);
    cudaGetSymbolAddress((void**)&wvH,   g_wvH);   cudaGetSymbolAddress((void**)&wvL,   g_wvL);
    cudaGetSymbolAddress((void**)&wfH,   g_wfH);   cudaGetSymbolAddress((void**)&wfL,   g_wfL);
    cudaGetSymbolAddress((void**)&w1H,   g_w1H);   cudaGetSymbolAddress((void**)&w1L,   g_w1L);
    cudaGetSymbolAddress((void**)&w2H,   g_w2H);   cudaGetSymbolAddress((void**)&w2L,   g_w2L);

    // ---- conversions ----
    {
        int n4;
        n4 = MKV * DM / 4;  cvt_hl<<<(n4 + 255) / 256, 256>>>(pred, predH, predL, n4);
        n4 = MQ * DM / 4;   cvt_hl<<<(n4 + 255) / 256, 256>>>(ent, entH, entL, n4);
        n4 = DM * DM / 4;
        cvt_hl<<<(n4 + 255) / 256, 256>>>(w_qs, wqH, wqL, n4);
        cvt_hl<<<(n4 + 255) / 256, 256>>>(w_ks, wkH, wkL, n4);
        cvt_hl<<<(n4 + 255) / 256, 256>>>(w_vs, wvH, wvL, n4);
        cvt_hl<<<(n4 + 255) / 256, 256>>>(w_fc, wfH, wfL, n4);
        n4 = DI * DM / 4;
        cvt_hl<<<(n4 + 255) / 256, 256>>>(w1, w1H, w1L, n4);
        cvt_hl<<<(n4 + 255) / 256, 256>>>(w2, w2H, w2L, n4);
    }

    dim3 blk(256);
    // K, V projections
    {
        dim3 grd(DM / GBN, (MKV + GBM - 1) / GBM);
        gemm_hl<<<grd, blk>>>(predH, predL, nullptr, wkH, wkL, b_ks, pK, nullptr, nullptr, MKV, DM, DM, 0);
        gemm_hl<<<grd, blk>>>(predH, predL, nullptr, wvH, wvL, b_vs, pV, nullptr, nullptr, MKV, DM, DM, 0);
    }
    // Q projection (padded layout)
    {
        dim3 grd(DM / GBN, (MQ + GBM - 1) / GBM);
        gemm_hl<<<grd, blk>>>(entH, entL, nullptr, wqH, wqL, b_qs, pQ, nullptr, nullptr, MQ, DM, DM, 0);
    }
    // attention -> ctx (bf16 HL, padded)
    {
        dim3 grd((Lq + 15) / 16, NH, BSZ);
        attn_flash<<<grd, 128>>>(pQ, pK, pV, amask, ctxH, ctxL, Lq, Lv);
    }
    // fc projection (gathers valid rows) + LN1 (emits x fp32 + HL)
    {
        dim3 grd(DM / GBN, (nv + GBM - 1) / GBM);
        gemm_hl<<<grd, blk>>>(ctxH, ctxL, gidx, wfH, wfL, b_fc, pT0, nullptr, nullptr, nv, DM, DM, 0);
        ln_res<<<nv, 128>>>(pT0, ent, gidx, ln1_g, ln1_b, pX, xH, xL);
    }
    // FFN
    {
        dim3 grd1(DI / GBN, (nv + GBM - 1) / GBM);
        gemm_hl<<<grd1, blk>>>(xH, xL, nullptr, w1H, w1L, b1, nullptr, hH, hL, nv, DI, DM, 1);
        dim3 grd2(DM / GBN, (nv + GBM - 1) / GBM);
        gemm_hl<<<grd2, blk>>>(hH, hL, nullptr, w2H, w2L, b2, pT0, nullptr, nullptr, nv, DM, DI, 0);
        ln_res<<<nv, 128>>>(pT0, pX, nullptr, ln2_g, ln2_b, (float*)d_out, nullptr, nullptr);
    }
}